// round 9
// baseline (speedup 1.0000x reference)
#include <cuda_runtime.h>
#include <math.h>

typedef unsigned long long ull;

// ---------------------------------------------------------------------------
// Scratch buffers (device globals; no allocation anywhere)
// b3r aliases g_buf1 during the encoder (b1 is dead after conv2 consumes it);
// bdr aliases g_buf3 during the decoder (b3 is dead after pvq).
// ---------------------------------------------------------------------------
__device__ float g_buf1[33554432];  // 32x64x128x128 (h1; enc b3r; deconv1 out)
__device__ float g_buf2[16777216];  // 32x128x64x64
__device__ float g_buf3[16777216];  // 32x128x64x64 (enc res state; dec bdr)
__device__ float g_buf4[4194304];   // 32x32x64x64  (res hidden, post-relu)
__device__ float g_z[8388608];      // 32x64x64x64
__device__ float g_q[8388608];      // 32x64x64x64
__device__ float g_d[16777216];     // 32x128x64x64 (dec res state)
__device__ float g_enorm[512];
__device__ float g_bsum[1024];

// ---------------------------------------------------------------------------
// Packed dual-fp32 helpers (FFMA2 via PTX fma.rn.f32x2; bit-identical to two
// scalar fmaf)
// ---------------------------------------------------------------------------
__device__ __forceinline__ ull pack2(float v) {
    ull p;
    asm("mov.b64 %0, {%1, %1};" : "=l"(p) : "f"(v));
    return p;
}
__device__ __forceinline__ void ffma2(ull& d, ull a, ull b) {
    asm("fma.rn.f32x2 %0, %1, %2, %0;" : "+l"(d) : "l"(a), "l"(b));
}
__device__ __forceinline__ float2 unpack2(ull p) {
    float2 r;
    asm("mov.b64 {%0, %1}, %2;" : "=f"(r.x), "=f"(r.y) : "l"(p));
    return r;
}

// ---------------------------------------------------------------------------
// cp.async helpers (4-byte, zfill when invalid)
// ---------------------------------------------------------------------------
__device__ __forceinline__ void cp_async4(unsigned smem_addr, const void* gptr, bool valid) {
    int sz = valid ? 4 : 0;
    asm volatile("cp.async.ca.shared.global [%0], [%1], 4, %2;\n"
                 :: "r"(smem_addr), "l"(gptr), "r"(sz));
}
__device__ __forceinline__ void cp_commit() {
    asm volatile("cp.async.commit_group;\n" ::: "memory");
}
template<int N>
__device__ __forceinline__ void cp_wait() {
    asm volatile("cp.async.wait_group %0;\n" :: "n"(N) : "memory");
}

// ---------------------------------------------------------------------------
// Generic direct conv: 16x16 out tile, 64 threads (8x8), each thread 2x2
// outputs x OCB oc (packed pairs, FFMA2). cp.async double-buffered over CB
// input-channel chunks. No input transform (relu hoisted to producers).
// in:  [N,Cin,Hin,Win]   w: [Cout,Cin,K,K]   out: [N,Cout,Hout,Wout]
// act: 0 none, 1 relu, 2 tanh. out_relu (optional): relu copy of the
// pre-activation result (used when act==0 and a relu'd view is needed).
// ---------------------------------------------------------------------------
template<int K, int S, int OCB, int CB>
__global__ void __launch_bounds__(64) conv2d_kernel(
    const float* __restrict__ in, const float* __restrict__ w,
    const float* __restrict__ bias, const float* __restrict__ resid,
    float* __restrict__ out, float* __restrict__ out_relu,
    int Cin, int Hin, int Win, int Cout, int Hout, int Wout,
    int pad, int act)
{
    constexpr int TILE = 16;
    constexpr int IT = TILE * S + K - S;
    constexpr int NP = OCB / 2;
    constexpr int SPAN = S + K;
    constexpr int IN_ELE = CB * IT * IT;
    constexpr int W_ELE  = CB * K * K * OCB;
    __shared__ __align__(16) float s_in[2][IN_ELE];
    __shared__ __align__(16) float s_w[2][W_ELE];

    const int groups = Cout / OCB;
    const int n   = blockIdx.z / groups;
    const int oc0 = (blockIdx.z % groups) * OCB;
    const int ox0 = blockIdx.x * TILE;
    const int oy0 = blockIdx.y * TILE;
    const int tx = threadIdx.x, ty = threadIdx.y;   // 8x8
    const int tid = ty * 8 + tx;

    ull acc[2][2][NP];
    #pragma unroll
    for (int a = 0; a < 2; a++)
        #pragma unroll
        for (int b = 0; b < 2; b++)
            #pragma unroll
            for (int p = 0; p < NP; p++) acc[a][b][p] = 0ULL;

    const int ix0 = ox0 * S - pad;
    const int iy0 = oy0 * S - pad;
    const int nchunks = (Cin + CB - 1) / CB;

    auto load_stage = [&](int st, int c0) {
        const int cb = min(CB, Cin - c0);
        unsigned sin = (unsigned)__cvta_generic_to_shared(&s_in[st][0]);
        for (int idx = tid; idx < cb * IT * IT; idx += 64) {
            int ci = idx / (IT * IT);
            int r  = idx - ci * IT * IT;
            int iy = r / IT, ix = r - iy * IT;
            int gy = iy0 + iy, gx = ix0 + ix;
            bool valid = (gy >= 0 && gy < Hin && gx >= 0 && gx < Win);
            int gyc = valid ? gy : 0, gxc = valid ? gx : 0;
            cp_async4(sin + idx * 4,
                      &in[((size_t)(n * Cin + c0 + ci) * Hin + gyc) * Win + gxc],
                      valid);
        }
        unsigned sw = (unsigned)__cvta_generic_to_shared(&s_w[st][0]);
        for (int idx = tid; idx < cb * K * K * OCB; idx += 64) {
            int o  = idx % OCB;
            int r  = idx / OCB;
            int ci = r / (K * K);
            int kk = r - ci * (K * K);
            cp_async4(sw + idx * 4,
                      &w[((size_t)(oc0 + o) * Cin + c0 + ci) * (K * K) + kk],
                      true);
        }
    };

    load_stage(0, 0);
    cp_commit();

    for (int ch = 0; ch < nchunks; ch++) {
        if (ch + 1 < nchunks) load_stage((ch + 1) & 1, (ch + 1) * CB);
        cp_commit();
        cp_wait<1>();
        __syncthreads();

        const int st = ch & 1;
        const int cb = min(CB, Cin - ch * CB);
        for (int ci = 0; ci < cb; ci++) {
            #pragma unroll
            for (int kh = 0; kh < K; kh++) {
                ull pk[2][SPAN];
                #pragma unroll
                for (int dy = 0; dy < 2; dy++) {
                    const float2* rp = reinterpret_cast<const float2*>(
                        &s_in[st][(ci * IT + (ty * 2 + dy) * S + kh) * IT + tx * 2 * S]);
                    float tmp[SPAN];
                    #pragma unroll
                    for (int i = 0; i < SPAN / 2; i++) {
                        float2 v2 = rp[i];
                        tmp[2 * i]     = v2.x;
                        tmp[2 * i + 1] = v2.y;
                    }
                    #pragma unroll
                    for (int i = 0; i < SPAN; i++) pk[dy][i] = pack2(tmp[i]);
                }
                #pragma unroll
                for (int kw = 0; kw < K; kw++) {
                    const ull* wq =
                        (const ull*)&s_w[st][((ci * K + kh) * K + kw) * OCB];
                    ull wv[NP];
                    #pragma unroll
                    for (int p = 0; p < NP; p++) wv[p] = wq[p];
                    #pragma unroll
                    for (int dy = 0; dy < 2; dy++) {
                        #pragma unroll
                        for (int dx = 0; dx < 2; dx++) {
                            #pragma unroll
                            for (int p = 0; p < NP; p++)
                                ffma2(acc[dy][dx][p], pk[dy][dx * S + kw], wv[p]);
                        }
                    }
                }
            }
        }
        __syncthreads();
    }

    #pragma unroll
    for (int dy = 0; dy < 2; dy++) {
        int oy = oy0 + ty * 2 + dy;
        if (oy >= Hout) continue;
        #pragma unroll
        for (int dx = 0; dx < 2; dx++) {
            int ox = ox0 + tx * 2 + dx;
            if (ox >= Wout) continue;
            #pragma unroll
            for (int p = 0; p < NP; p++) {
                float2 r2 = unpack2(acc[dy][dx][p]);
                #pragma unroll
                for (int h = 0; h < 2; h++) {
                    int o = 2 * p + h;
                    float v = (h ? r2.y : r2.x) + bias[oc0 + o];
                    int oidx = ((n * Cout + oc0 + o) * Hout + oy) * Wout + ox;
                    if (resid) v += resid[oidx];
                    if (act == 1)      v = fmaxf(v, 0.f);
                    else if (act == 2) v = tanhf(v);
                    out[oidx] = v;
                    if (out_relu) out_relu[oidx] = fmaxf(v, 0.f);
                }
            }
        }
    }
}

// ---------------------------------------------------------------------------
// ConvTranspose2d(k=4, s=2, p=1), packed oc pairs + register row caching +
// cp.async double buffering.
// Parity decomposition: kh -> (py=(kh+1)&1, dih: 0->+1, 1,2->0, 3->-1).
// ---------------------------------------------------------------------------
template<int COB, int CB>
__global__ void __launch_bounds__(128) deconv_k4s2_kernel(
    const float* __restrict__ in, const float* __restrict__ w,
    const float* __restrict__ bias, float* __restrict__ out,
    int Cin, int Hin, int Win, int Cout, int act)
{
    constexpr int NP = COB / 2;
    constexpr int IN_ELE = CB * 324;
    constexpr int W_ELE  = CB * 16 * COB;
    __shared__ __align__(16) float s_in[2][IN_ELE];
    __shared__ __align__(16) float s_w[2][W_ELE];

    const int Hout = Hin * 2, Wout = Win * 2;
    const int groups = (Cout + COB - 1) / COB;
    const int n   = blockIdx.z / groups;
    const int co0 = (blockIdx.z % groups) * COB;
    const int uw0 = blockIdx.x * 16, uh0 = blockIdx.y * 16;
    const int tx = threadIdx.x, ty = threadIdx.y;   // 8x16
    const int tid = ty * 8 + tx;

    ull acc[2][2][2][NP];   // [j(uw)][py][px][pair]
    #pragma unroll
    for (int j = 0; j < 2; j++)
        #pragma unroll
        for (int py = 0; py < 2; py++)
            #pragma unroll
            for (int px = 0; px < 2; px++)
                #pragma unroll
                for (int p = 0; p < NP; p++) acc[j][py][px][p] = 0ULL;

    const int nchunks = (Cin + CB - 1) / CB;

    auto load_stage = [&](int st, int c0) {
        const int cb = min(CB, Cin - c0);
        unsigned sin = (unsigned)__cvta_generic_to_shared(&s_in[st][0]);
        for (int idx = tid; idx < cb * 324; idx += 128) {
            int ci = idx / 324;
            int r  = idx - ci * 324;
            int iy = r / 18, ix = r - iy * 18;
            int gy = uh0 - 1 + iy, gx = uw0 - 1 + ix;
            bool valid = (gy >= 0 && gy < Hin && gx >= 0 && gx < Win);
            int gyc = valid ? gy : 0, gxc = valid ? gx : 0;
            cp_async4(sin + idx * 4,
                      &in[((size_t)(n * Cin + c0 + ci) * Hin + gyc) * Win + gxc],
                      valid);
        }
        unsigned sw = (unsigned)__cvta_generic_to_shared(&s_w[st][0]);
        for (int idx = tid; idx < cb * 16 * COB; idx += 128) {
            int o  = idx % COB;
            int r  = idx / COB;
            int ci = r / 16;
            int kk = r - ci * 16;
            bool valid = (co0 + o < Cout);
            int oc = valid ? (co0 + o) : 0;
            cp_async4(sw + idx * 4,
                      &w[((size_t)(c0 + ci) * Cout + oc) * 16 + kk],
                      valid);
        }
    };

    load_stage(0, 0);
    cp_commit();

    for (int ch = 0; ch < nchunks; ch++) {
        if (ch + 1 < nchunks) load_stage((ch + 1) & 1, (ch + 1) * CB);
        cp_commit();
        cp_wait<1>();
        __syncthreads();

        const int st = ch & 1;
        const int cb = min(CB, Cin - ch * CB);
        for (int ci = 0; ci < cb; ci++) {
            ull pk[3][4];
            #pragma unroll
            for (int r = 0; r < 3; r++) {
                const float2* rp = reinterpret_cast<const float2*>(
                    &s_in[st][(ci * 18 + ty + r) * 18 + tx * 2]);
                float2 a = rp[0], b = rp[1];
                pk[r][0] = pack2(a.x); pk[r][1] = pack2(a.y);
                pk[r][2] = pack2(b.x); pk[r][3] = pack2(b.y);
            }
            #pragma unroll
            for (int kh = 0; kh < 4; kh++) {
                const int py = (kh + 1) & 1;
                const int ro = (kh == 0) ? 2 : ((kh == 3) ? 0 : 1);
                #pragma unroll
                for (int kw = 0; kw < 4; kw++) {
                    const int px = (kw + 1) & 1;
                    const int co = (kw == 0) ? 2 : ((kw == 3) ? 0 : 1);
                    const ull* wq =
                        (const ull*)&s_w[st][(ci * 16 + kh * 4 + kw) * COB];
                    ull wv[NP];
                    #pragma unroll
                    for (int p = 0; p < NP; p++) wv[p] = wq[p];
                    #pragma unroll
                    for (int j = 0; j < 2; j++) {
                        #pragma unroll
                        for (int p = 0; p < NP; p++)
                            ffma2(acc[j][py][px][p], pk[ro][j + co], wv[p]);
                    }
                }
            }
        }
        __syncthreads();
    }

    #pragma unroll
    for (int j = 0; j < 2; j++) {
        #pragma unroll
        for (int py = 0; py < 2; py++) {
            int oy = 2 * (uh0 + ty) + py;
            #pragma unroll
            for (int px = 0; px < 2; px++) {
                int ox = 2 * (uw0 + tx * 2 + j) + px;
                #pragma unroll
                for (int p = 0; p < NP; p++) {
                    float2 r2 = unpack2(acc[j][py][px][p]);
                    #pragma unroll
                    for (int h = 0; h < 2; h++) {
                        int o = 2 * p + h;
                        if (co0 + o < Cout) {
                            float v = (h ? r2.y : r2.x) + bias[co0 + o];
                            if (act == 1)      v = fmaxf(v, 0.f);
                            else if (act == 2) v = tanhf(v);
                            out[((size_t)(n * Cout + co0 + o) * Hout + oy) * Wout + ox] = v;
                        }
                    }
                }
            }
        }
    }
}

// ---------------------------------------------------------------------------
// VQ: per-vector argmin over 512 codes (packed code-pair dots),
// write quantized, per-block loss sums.
// ---------------------------------------------------------------------------
__global__ void vq_prep_kernel(const float* __restrict__ cb, float* __restrict__ enorm)
{
    int k = blockIdx.x * blockDim.x + threadIdx.x;
    if (k < 512) {
        float s = 0.f;
        #pragma unroll
        for (int d = 0; d < 64; d++) { float v = cb[k * 64 + d]; s += v * v; }
        enorm[k] = s;
    }
}

__global__ void __launch_bounds__(128) vq_kernel(
    const float* __restrict__ z, const float* __restrict__ cb,
    const float* __restrict__ enorm, float* __restrict__ q,
    float* __restrict__ bsum)
{
    __shared__ __align__(16) float sc[64 * 66];
    __shared__ float se[64];
    __shared__ float sred[128];

    const int tid = threadIdx.x;
    const int v   = blockIdx.x * 128 + tid;
    const int b   = v >> 12;
    const int hw  = v & 4095;

    const float* zp = z + b * 64 * 4096 + hw;
    float zr[64];
    float znorm = 0.f;
    #pragma unroll
    for (int d = 0; d < 64; d++) { zr[d] = zp[d * 4096]; znorm += zr[d] * zr[d]; }

    float best = 3.402823e38f;
    int   bi   = 0;
    for (int c0 = 0; c0 < 512; c0 += 64) {
        __syncthreads();
        for (int i = tid; i < 4096; i += 128) {
            int c = i >> 6, d = i & 63;
            sc[d * 66 + c] = cb[(c0 + c) * 64 + d];
        }
        if (tid < 64) se[tid] = enorm[c0 + tid];
        __syncthreads();
        #pragma unroll
        for (int g = 0; g < 4; g++) {
            ull dp[8];
            #pragma unroll
            for (int p = 0; p < 8; p++) dp[p] = 0ULL;
            #pragma unroll
            for (int d = 0; d < 64; d++) {
                ull z2 = pack2(zr[d]);
                const ull* row = (const ull*)&sc[d * 66 + g * 16];
                #pragma unroll
                for (int p = 0; p < 8; p++) ffma2(dp[p], z2, row[p]);
            }
            #pragma unroll
            for (int p = 0; p < 8; p++) {
                float2 dd = unpack2(dp[p]);
                int c = g * 16 + 2 * p;
                float dist0 = znorm - 2.f * dd.x + se[c];
                if (dist0 < best) { best = dist0; bi = c0 + c; }
                float dist1 = znorm - 2.f * dd.y + se[c + 1];
                if (dist1 < best) { best = dist1; bi = c0 + c + 1; }
            }
        }
    }

    const float* e = cb + bi * 64;
    float* qp = q + b * 64 * 4096 + hw;
    float err = 0.f;
    #pragma unroll
    for (int d = 0; d < 64; d++) {
        float ev = e[d];
        float df = ev - zr[d];
        err += df * df;
        qp[d * 4096] = ev;
    }

    sred[tid] = err;
    __syncthreads();
    for (int s = 64; s > 0; s >>= 1) {
        if (tid < s) sred[tid] += sred[tid + s];
        __syncthreads();
    }
    if (tid == 0) bsum[blockIdx.x] = sred[0];
}

__global__ void finalize_kernel(const float* __restrict__ bsum, float* __restrict__ out_loss)
{
    __shared__ float s[256];
    int t = threadIdx.x;
    float v = 0.f;
    for (int i = t; i < 1024; i += 256) v += bsum[i];
    s[t] = v;
    __syncthreads();
    for (int k = 128; k > 0; k >>= 1) {
        if (t < k) s[t] += s[t + k];
        __syncthreads();
    }
    if (t == 0) out_loss[0] = 1.25f * s[0] / 8388608.0f;
}

// ---------------------------------------------------------------------------
// Launcher
// ---------------------------------------------------------------------------
extern "C" void kernel_launch(void* const* d_in, const int* in_sizes, int n_in,
                              void* d_out, int out_size)
{
    const float* x        = (const float*)d_in[0];
    const float* enc_w1   = (const float*)d_in[1];
    const float* enc_b1   = (const float*)d_in[2];
    const float* enc_w2   = (const float*)d_in[3];
    const float* enc_b2   = (const float*)d_in[4];
    const float* enc_w3   = (const float*)d_in[5];
    const float* enc_b3   = (const float*)d_in[6];
    const float* enc_rw1  = (const float*)d_in[7];
    const float* enc_rb1  = (const float*)d_in[8];
    const float* enc_rw2  = (const float*)d_in[9];
    const float* enc_rb2  = (const float*)d_in[10];
    const float* pvq_w    = (const float*)d_in[11];
    const float* pvq_b    = (const float*)d_in[12];
    const float* codebook = (const float*)d_in[13];
    const float* dec_w1   = (const float*)d_in[14];
    const float* dec_b1   = (const float*)d_in[15];
    const float* dec_rw1  = (const float*)d_in[16];
    const float* dec_rb1  = (const float*)d_in[17];
    const float* dec_rw2  = (const float*)d_in[18];
    const float* dec_rb2  = (const float*)d_in[19];
    const float* dt1_w    = (const float*)d_in[20];
    const float* dt1_b    = (const float*)d_in[21];
    const float* dt2_w    = (const float*)d_in[22];
    const float* dt2_b    = (const float*)d_in[23];
    float* outp = (float*)d_out;

    static float *b1 = nullptr, *b2, *b3, *b4, *bz, *bq, *bd, *pe, *pbs;
    if (!b1) {
        cudaGetSymbolAddress((void**)&b1,  g_buf1);
        cudaGetSymbolAddress((void**)&b2,  g_buf2);
        cudaGetSymbolAddress((void**)&b3,  g_buf3);
        cudaGetSymbolAddress((void**)&b4,  g_buf4);
        cudaGetSymbolAddress((void**)&bz,  g_z);
        cudaGetSymbolAddress((void**)&bq,  g_q);
        cudaGetSymbolAddress((void**)&bd,  g_d);
        cudaGetSymbolAddress((void**)&pe,  g_enorm);
        cudaGetSymbolAddress((void**)&pbs, g_bsum);
    }
    float* b3r = b1;   // relu view of enc res state (b1 dead after conv2)
    float* bdr = b3;   // relu view of dec res state (b3 dead after pvq)

    const dim3 blk(8, 8);      // 64 threads, 16x16 output tile
    const dim3 dblk(8, 16);
    const int N = 32;

    // ---- Encoder ----
    // conv1: 3->64, k4 s2 p1, relu  (256 -> 128)
    conv2d_kernel<4, 2, 16, 4><<<dim3(8, 8, N * (64 / 16)), blk>>>(
        x, enc_w1, enc_b1, nullptr, b1, nullptr, 3, 256, 256, 64, 128, 128, 1, 1);
    // conv2: 64->128, k4 s2 p1, relu  (128 -> 64)
    conv2d_kernel<4, 2, 16, 4><<<dim3(4, 4, N * (128 / 16)), blk>>>(
        b1, enc_w2, enc_b2, nullptr, b2, nullptr, 64, 128, 128, 128, 64, 64, 1, 1);
    // conv3: 128->128, k3 s1 p1; writes pre-act b3 + relu copy b3r
    conv2d_kernel<3, 1, 16, 8><<<dim3(4, 4, N * (128 / 16)), blk>>>(
        b2, enc_w3, enc_b3, nullptr, b3, b3r, 128, 64, 64, 128, 64, 64, 1, 0);
    // residual stack x2: 3x3 reads relu view, writes relu(h); 1x1 updates both views
    for (int i = 0; i < 2; i++) {
        const float* w1p = enc_rw1 + (size_t)i * 32 * 128 * 9;
        const float* b1p = enc_rb1 + i * 32;
        const float* w2p = enc_rw2 + (size_t)i * 128 * 32;
        const float* b2p = enc_rb2 + i * 128;
        conv2d_kernel<3, 1, 16, 8><<<dim3(4, 4, N * (32 / 16)), blk>>>(
            b3r, w1p, b1p, nullptr, b4, nullptr, 128, 64, 64, 32, 64, 64, 1, 1);
        conv2d_kernel<1, 1, 16, 16><<<dim3(4, 4, N * (128 / 16)), blk>>>(
            b4, w2p, b2p, b3, b3, b3r, 32, 64, 64, 128, 64, 64, 0, 0);
    }
    // pre-VQ 1x1: 128->64 (reads relu(x_final))
    conv2d_kernel<1, 1, 16, 16><<<dim3(4, 4, N * (64 / 16)), blk>>>(
        b3r, pvq_w, pvq_b, nullptr, bz, nullptr, 128, 64, 64, 64, 64, 64, 0, 0);

    // ---- VQ ----
    vq_prep_kernel<<<2, 256>>>(codebook, pe);
    vq_kernel<<<1024, 128>>>(bz, codebook, pe, bq, pbs);

    // ---- Decoder ----
    // dec conv1: 64->128, k3 s1 p1; writes pre-act bd + relu copy bdr
    conv2d_kernel<3, 1, 16, 8><<<dim3(4, 4, N * (128 / 16)), blk>>>(
        bq, dec_w1, dec_b1, nullptr, bd, bdr, 64, 64, 64, 128, 64, 64, 1, 0);
    // residual stack x2
    for (int i = 0; i < 2; i++) {
        const float* w1p = dec_rw1 + (size_t)i * 32 * 128 * 9;
        const float* b1p = dec_rb1 + i * 32;
        const float* w2p = dec_rw2 + (size_t)i * 128 * 32;
        const float* b2p = dec_rb2 + i * 128;
        conv2d_kernel<3, 1, 16, 8><<<dim3(4, 4, N * (32 / 16)), blk>>>(
            bdr, w1p, b1p, nullptr, b4, nullptr, 128, 64, 64, 32, 64, 64, 1, 1);
        conv2d_kernel<1, 1, 16, 16><<<dim3(4, 4, N * (128 / 16)), blk>>>(
            b4, w2p, b2p, bd, bd, bdr, 32, 64, 64, 128, 64, 64, 0, 0);
    }
    // deconv1: 128->64, relu  (64 -> 128); reads relu(x_final)
    deconv_k4s2_kernel<8, 8><<<dim3(4, 4, N * (64 / 8)), dblk>>>(
        bdr, dt1_w, dt1_b, b1, 128, 64, 64, 64, 1);
    // deconv2: 64->3, tanh  (128 -> 256), COB=4
    deconv_k4s2_kernel<4, 8><<<dim3(8, 8, N * 1), dblk>>>(
        b1, dt2_w, dt2_b, outp, 64, 128, 128, 3, 2);

    // vq_loss -> last output element (deterministic fixed-order reduction)
    finalize_kernel<<<1, 256>>>(pbs, outp + (out_size - 1));
}

// round 10
// speedup vs baseline: 1.0541x; 1.0541x over previous
#include <cuda_runtime.h>
#include <math.h>

typedef unsigned long long ull;

// ---------------------------------------------------------------------------
// Scratch buffers (device globals; no allocation anywhere)
// ---------------------------------------------------------------------------
__device__ float g_buf1[33554432];  // 32x64x128x128 (h1, later deconv1 out)
__device__ float g_buf2[16777216];  // 32x128x64x64
__device__ float g_buf3[16777216];  // 32x128x64x64 (enc res state)
__device__ float g_buf4[4194304];   // 32x32x64x64  (res hidden)
__device__ float g_z[8388608];      // 32x64x64x64
__device__ float g_q[8388608];      // 32x64x64x64
__device__ float g_d[16777216];     // 32x128x64x64 (dec res state)
__device__ float g_enorm[512];
__device__ float g_bsum[1024];

// ---------------------------------------------------------------------------
// Packed dual-fp32 helpers (FFMA2 via PTX fma.rn.f32x2; bit-identical to two
// scalar fmaf)
// ---------------------------------------------------------------------------
__device__ __forceinline__ ull pack2(float v) {
    ull p;
    asm("mov.b64 %0, {%1, %1};" : "=l"(p) : "f"(v));
    return p;
}
__device__ __forceinline__ void ffma2(ull& d, ull a, ull b) {
    asm("fma.rn.f32x2 %0, %1, %2, %0;" : "+l"(d) : "l"(a), "l"(b));
}
__device__ __forceinline__ float2 unpack2(ull p) {
    float2 r;
    asm("mov.b64 {%0, %1}, %2;" : "=f"(r.x), "=f"(r.y) : "l"(p));
    return r;
}
// Load NP packed weight pairs with 128-bit LDS (callers guarantee 16B align)
template<int NP>
__device__ __forceinline__ void load_w128(ull* wv, const float* p) {
    const ulonglong2* wq = reinterpret_cast<const ulonglong2*>(p);
    #pragma unroll
    for (int i = 0; i < NP / 2; i++) {
        ulonglong2 t = wq[i];
        wv[2 * i]     = t.x;
        wv[2 * i + 1] = t.y;
    }
}

// ---------------------------------------------------------------------------
// Generic direct conv (R3 geometry): 16x16 out tile, 64 threads (8x8),
// each thread 2x2 outputs x OCB oc (packed in pairs).
// Inner loop: per (ci,kh) the contiguous S+K input span is loaded once via
// aligned float2 LDS and packed once; weights broadcast as 128-bit loads.
// in:  [N,Cin,Hin,Win]   w: [Cout,Cin,K,K]   out: [N,Cout,Hout,Wout]
// act: 0 none, 1 relu, 2 tanh.  in_relu applies relu when reading input.
// ---------------------------------------------------------------------------
template<int K, int S, int OCB, int CB>
__global__ void __launch_bounds__(64) conv2d_kernel(
    const float* __restrict__ in, const float* __restrict__ w,
    const float* __restrict__ bias, const float* __restrict__ resid,
    float* __restrict__ out,
    int Cin, int Hin, int Win, int Cout, int Hout, int Wout,
    int pad, int in_relu, int act)
{
    constexpr int TILE = 16;
    constexpr int IT = TILE * S + K - S;   // input tile span
    constexpr int NP = OCB / 2;
    constexpr int SPAN = S + K;            // per-row contiguous input span (even)
    __shared__ __align__(16) float s_in[CB * IT * IT];
    __shared__ __align__(16) float s_w[CB * K * K * OCB];

    const int groups = Cout / OCB;
    const int n   = blockIdx.z / groups;
    const int oc0 = (blockIdx.z % groups) * OCB;
    const int ox0 = blockIdx.x * TILE;
    const int oy0 = blockIdx.y * TILE;
    const int tx = threadIdx.x, ty = threadIdx.y;   // 8x8
    const int tid = ty * 8 + tx;

    ull acc[2][2][NP];
    #pragma unroll
    for (int a = 0; a < 2; a++)
        #pragma unroll
        for (int b = 0; b < 2; b++)
            #pragma unroll
            for (int p = 0; p < NP; p++) acc[a][b][p] = 0ULL;

    const int ix0 = ox0 * S - pad;
    const int iy0 = oy0 * S - pad;

    for (int c0 = 0; c0 < Cin; c0 += CB) {
        const int cb = min(CB, Cin - c0);

        for (int idx = tid; idx < cb * IT * IT; idx += 64) {
            int ci = idx / (IT * IT);
            int r  = idx - ci * IT * IT;
            int iy = r / IT, ix = r - iy * IT;
            int gy = iy0 + iy, gx = ix0 + ix;
            float v = 0.f;
            if (gy >= 0 && gy < Hin && gx >= 0 && gx < Win)
                v = in[((n * Cin + c0 + ci) * Hin + gy) * Win + gx];
            if (in_relu) v = fmaxf(v, 0.f);
            s_in[idx] = v;
        }
        for (int idx = tid; idx < cb * K * K * OCB; idx += 64) {
            int o  = idx % OCB;
            int r  = idx / OCB;
            int ci = r / (K * K);
            int kk = r - ci * (K * K);
            s_w[idx] = w[((oc0 + o) * Cin + c0 + ci) * (K * K) + kk];
        }
        __syncthreads();

        for (int ci = 0; ci < cb; ci++) {
            #pragma unroll
            for (int kh = 0; kh < K; kh++) {
                // cache + pack the two input rows for dy=0,1
                ull pk[2][SPAN];
                #pragma unroll
                for (int dy = 0; dy < 2; dy++) {
                    const float2* rp = reinterpret_cast<const float2*>(
                        &s_in[(ci * IT + (ty * 2 + dy) * S + kh) * IT + tx * 2 * S]);
                    float tmp[SPAN];
                    #pragma unroll
                    for (int i = 0; i < SPAN / 2; i++) {
                        float2 v2 = rp[i];
                        tmp[2 * i]     = v2.x;
                        tmp[2 * i + 1] = v2.y;
                    }
                    #pragma unroll
                    for (int i = 0; i < SPAN; i++) pk[dy][i] = pack2(tmp[i]);
                }
                #pragma unroll
                for (int kw = 0; kw < K; kw++) {
                    ull wv[NP];
                    load_w128<NP>(wv, &s_w[((ci * K + kh) * K + kw) * OCB]);
                    #pragma unroll
                    for (int dy = 0; dy < 2; dy++) {
                        #pragma unroll
                        for (int dx = 0; dx < 2; dx++) {
                            #pragma unroll
                            for (int p = 0; p < NP; p++)
                                ffma2(acc[dy][dx][p], pk[dy][dx * S + kw], wv[p]);
                        }
                    }
                }
            }
        }
        __syncthreads();
    }

    #pragma unroll
    for (int dy = 0; dy < 2; dy++) {
        int oy = oy0 + ty * 2 + dy;
        if (oy >= Hout) continue;
        #pragma unroll
        for (int dx = 0; dx < 2; dx++) {
            int ox = ox0 + tx * 2 + dx;
            if (ox >= Wout) continue;
            #pragma unroll
            for (int p = 0; p < NP; p++) {
                float2 r2 = unpack2(acc[dy][dx][p]);
                #pragma unroll
                for (int h = 0; h < 2; h++) {
                    int o = 2 * p + h;
                    float v = (h ? r2.y : r2.x) + bias[oc0 + o];
                    int oidx = ((n * Cout + oc0 + o) * Hout + oy) * Wout + ox;
                    if (resid) v += resid[oidx];
                    if (act == 1)      v = fmaxf(v, 0.f);
                    else if (act == 2) v = tanhf(v);
                    out[oidx] = v;
                }
            }
        }
    }
}

// ---------------------------------------------------------------------------
// ConvTranspose2d(k=4, s=2, p=1), packed oc pairs + register row caching.
// Parity decomposition: kh -> (py=(kh+1)&1, dih: 0->+1, 1,2->0, 3->-1).
// Per ci: 3 input rows x 4 cols cached and packed once.
// ---------------------------------------------------------------------------
template<int COB, int CB>
__global__ void __launch_bounds__(128) deconv_k4s2_kernel(
    const float* __restrict__ in, const float* __restrict__ w,
    const float* __restrict__ bias, float* __restrict__ out,
    int Cin, int Hin, int Win, int Cout, int act)
{
    constexpr int NP = COB / 2;
    __shared__ __align__(16) float s_in[CB * 18 * 18];
    __shared__ __align__(16) float s_w[CB * 16 * COB];

    const int Hout = Hin * 2, Wout = Win * 2;
    const int groups = (Cout + COB - 1) / COB;
    const int n   = blockIdx.z / groups;
    const int co0 = (blockIdx.z % groups) * COB;
    const int uw0 = blockIdx.x * 16, uh0 = blockIdx.y * 16;
    const int tx = threadIdx.x, ty = threadIdx.y;   // 8x16
    const int tid = ty * 8 + tx;

    ull acc[2][2][2][NP];   // [j(uw)][py][px][pair]
    #pragma unroll
    for (int j = 0; j < 2; j++)
        #pragma unroll
        for (int py = 0; py < 2; py++)
            #pragma unroll
            for (int px = 0; px < 2; px++)
                #pragma unroll
                for (int p = 0; p < NP; p++) acc[j][py][px][p] = 0ULL;

    for (int c0 = 0; c0 < Cin; c0 += CB) {
        const int cb = min(CB, Cin - c0);
        for (int idx = tid; idx < cb * 324; idx += 128) {
            int ci = idx / 324;
            int r  = idx - ci * 324;
            int iy = r / 18, ix = r - iy * 18;
            int gy = uh0 - 1 + iy, gx = uw0 - 1 + ix;
            float v = 0.f;
            if (gy >= 0 && gy < Hin && gx >= 0 && gx < Win)
                v = in[((n * Cin + c0 + ci) * Hin + gy) * Win + gx];
            s_in[idx] = v;
        }
        for (int idx = tid; idx < cb * 16 * COB; idx += 128) {
            int o  = idx % COB;
            int r  = idx / COB;
            int ci = r / 16;
            int kk = r - ci * 16;
            float v = 0.f;
            if (co0 + o < Cout)
                v = w[((c0 + ci) * Cout + co0 + o) * 16 + kk];
            s_w[idx] = v;
        }
        __syncthreads();

        for (int ci = 0; ci < cb; ci++) {
            // cache 3 rows x 4 cols of input, pack once
            ull pk[3][4];
            #pragma unroll
            for (int r = 0; r < 3; r++) {
                const float2* rp = reinterpret_cast<const float2*>(
                    &s_in[(ci * 18 + ty + r) * 18 + tx * 2]);
                float2 a = rp[0], b = rp[1];
                pk[r][0] = pack2(a.x); pk[r][1] = pack2(a.y);
                pk[r][2] = pack2(b.x); pk[r][3] = pack2(b.y);
            }
            #pragma unroll
            for (int kh = 0; kh < 4; kh++) {
                const int py = (kh + 1) & 1;
                const int ro = (kh == 0) ? 2 : ((kh == 3) ? 0 : 1);  // dih+1
                #pragma unroll
                for (int kw = 0; kw < 4; kw++) {
                    const int px = (kw + 1) & 1;
                    const int co = (kw == 0) ? 2 : ((kw == 3) ? 0 : 1);  // diw+1
                    ull wv[NP];
                    load_w128<NP>(wv, &s_w[(ci * 16 + kh * 4 + kw) * COB]);
                    #pragma unroll
                    for (int j = 0; j < 2; j++) {
                        #pragma unroll
                        for (int p = 0; p < NP; p++)
                            ffma2(acc[j][py][px][p], pk[ro][j + co], wv[p]);
                    }
                }
            }
        }
        __syncthreads();
    }

    #pragma unroll
    for (int j = 0; j < 2; j++) {
        #pragma unroll
        for (int py = 0; py < 2; py++) {
            int oy = 2 * (uh0 + ty) + py;
            #pragma unroll
            for (int px = 0; px < 2; px++) {
                int ox = 2 * (uw0 + tx * 2 + j) + px;
                #pragma unroll
                for (int p = 0; p < NP; p++) {
                    float2 r2 = unpack2(acc[j][py][px][p]);
                    #pragma unroll
                    for (int h = 0; h < 2; h++) {
                        int o = 2 * p + h;
                        if (co0 + o < Cout) {
                            float v = (h ? r2.y : r2.x) + bias[co0 + o];
                            if (act == 1)      v = fmaxf(v, 0.f);
                            else if (act == 2) v = tanhf(v);
                            out[((n * Cout + co0 + o) * Hout + oy) * Wout + ox] = v;
                        }
                    }
                }
            }
        }
    }
}

// ---------------------------------------------------------------------------
// VQ: per-vector argmin over 512 codes (packed code-pair dots),
// write quantized, per-block loss sums.
// ---------------------------------------------------------------------------
__global__ void vq_prep_kernel(const float* __restrict__ cb, float* __restrict__ enorm)
{
    int k = blockIdx.x * blockDim.x + threadIdx.x;
    if (k < 512) {
        float s = 0.f;
        #pragma unroll
        for (int d = 0; d < 64; d++) { float v = cb[k * 64 + d]; s += v * v; }
        enorm[k] = s;
    }
}

__global__ void __launch_bounds__(128) vq_kernel(
    const float* __restrict__ z, const float* __restrict__ cb,
    const float* __restrict__ enorm, float* __restrict__ q,
    float* __restrict__ bsum)
{
    // transposed codebook chunk: sc[d*66 + c], c in [0,64). stride 66 keeps
    // ull reads aligned (even) and spreads transpose-write banks.
    __shared__ __align__(16) float sc[64 * 66];
    __shared__ float se[64];
    __shared__ float sred[128];

    const int tid = threadIdx.x;
    const int v   = blockIdx.x * 128 + tid;
    const int b   = v >> 12;
    const int hw  = v & 4095;

    const float* zp = z + b * 64 * 4096 + hw;
    float zr[64];
    float znorm = 0.f;
    #pragma unroll
    for (int d = 0; d < 64; d++) { zr[d] = zp[d * 4096]; znorm += zr[d] * zr[d]; }

    float best = 3.402823e38f;
    int   bi   = 0;
    for (int c0 = 0; c0 < 512; c0 += 64) {
        __syncthreads();
        for (int i = tid; i < 4096; i += 128) {
            int c = i >> 6, d = i & 63;
            sc[d * 66 + c] = cb[(c0 + c) * 64 + d];
        }
        if (tid < 64) se[tid] = enorm[c0 + tid];
        __syncthreads();
        // 4 groups of 16 codes (8 packed pairs each)
        #pragma unroll
        for (int g = 0; g < 4; g++) {
            ull dp[8];
            #pragma unroll
            for (int p = 0; p < 8; p++) dp[p] = 0ULL;
            #pragma unroll
            for (int d = 0; d < 64; d++) {
                ull z2 = pack2(zr[d]);
                const ull* row = (const ull*)&sc[d * 66 + g * 16];
                #pragma unroll
                for (int p = 0; p < 8; p++) ffma2(dp[p], z2, row[p]);
            }
            #pragma unroll
            for (int p = 0; p < 8; p++) {
                float2 dd = unpack2(dp[p]);
                int c = g * 16 + 2 * p;
                float dist0 = znorm - 2.f * dd.x + se[c];
                if (dist0 < best) { best = dist0; bi = c0 + c; }
                float dist1 = znorm - 2.f * dd.y + se[c + 1];
                if (dist1 < best) { best = dist1; bi = c0 + c + 1; }
            }
        }
    }

    const float* e = cb + bi * 64;
    float* qp = q + b * 64 * 4096 + hw;
    float err = 0.f;
    #pragma unroll
    for (int d = 0; d < 64; d++) {
        float ev = e[d];
        float df = ev - zr[d];
        err += df * df;
        qp[d * 4096] = ev;
    }

    sred[tid] = err;
    __syncthreads();
    for (int s = 64; s > 0; s >>= 1) {
        if (tid < s) sred[tid] += sred[tid + s];
        __syncthreads();
    }
    if (tid == 0) bsum[blockIdx.x] = sred[0];
}

__global__ void finalize_kernel(const float* __restrict__ bsum, float* __restrict__ out_loss)
{
    __shared__ float s[256];
    int t = threadIdx.x;
    float v = 0.f;
    for (int i = t; i < 1024; i += 256) v += bsum[i];
    s[t] = v;
    __syncthreads();
    for (int k = 128; k > 0; k >>= 1) {
        if (t < k) s[t] += s[t + k];
        __syncthreads();
    }
    if (t == 0) out_loss[0] = 1.25f * s[0] / 8388608.0f;
}

// ---------------------------------------------------------------------------
// Launcher
// ---------------------------------------------------------------------------
extern "C" void kernel_launch(void* const* d_in, const int* in_sizes, int n_in,
                              void* d_out, int out_size)
{
    const float* x        = (const float*)d_in[0];
    const float* enc_w1   = (const float*)d_in[1];
    const float* enc_b1   = (const float*)d_in[2];
    const float* enc_w2   = (const float*)d_in[3];
    const float* enc_b2   = (const float*)d_in[4];
    const float* enc_w3   = (const float*)d_in[5];
    const float* enc_b3   = (const float*)d_in[6];
    const float* enc_rw1  = (const float*)d_in[7];
    const float* enc_rb1  = (const float*)d_in[8];
    const float* enc_rw2  = (const float*)d_in[9];
    const float* enc_rb2  = (const float*)d_in[10];
    const float* pvq_w    = (const float*)d_in[11];
    const float* pvq_b    = (const float*)d_in[12];
    const float* codebook = (const float*)d_in[13];
    const float* dec_w1   = (const float*)d_in[14];
    const float* dec_b1   = (const float*)d_in[15];
    const float* dec_rw1  = (const float*)d_in[16];
    const float* dec_rb1  = (const float*)d_in[17];
    const float* dec_rw2  = (const float*)d_in[18];
    const float* dec_rb2  = (const float*)d_in[19];
    const float* dt1_w    = (const float*)d_in[20];
    const float* dt1_b    = (const float*)d_in[21];
    const float* dt2_w    = (const float*)d_in[22];
    const float* dt2_b    = (const float*)d_in[23];
    float* outp = (float*)d_out;

    static float *b1 = nullptr, *b2, *b3, *b4, *bz, *bq, *bd, *pe, *pbs;
    if (!b1) {
        cudaGetSymbolAddress((void**)&b1,  g_buf1);
        cudaGetSymbolAddress((void**)&b2,  g_buf2);
        cudaGetSymbolAddress((void**)&b3,  g_buf3);
        cudaGetSymbolAddress((void**)&b4,  g_buf4);
        cudaGetSymbolAddress((void**)&bz,  g_z);
        cudaGetSymbolAddress((void**)&bq,  g_q);
        cudaGetSymbolAddress((void**)&bd,  g_d);
        cudaGetSymbolAddress((void**)&pe,  g_enorm);
        cudaGetSymbolAddress((void**)&pbs, g_bsum);
    }

    const dim3 blk(8, 8);      // 64 threads, 16x16 output tile
    const dim3 dblk(8, 16);
    const int N = 32;

    // ---- Encoder ----
    // conv1: 3->64, k4 s2 p1, relu  (256 -> 128)
    conv2d_kernel<4, 2, 16, 4><<<dim3(8, 8, N * (64 / 16)), blk>>>(
        x, enc_w1, enc_b1, nullptr, b1, 3, 256, 256, 64, 128, 128, 1, 0, 1);
    // conv2: 64->128, k4 s2 p1, relu  (128 -> 64)
    conv2d_kernel<4, 2, 16, 4><<<dim3(4, 4, N * (128 / 16)), blk>>>(
        b1, enc_w2, enc_b2, nullptr, b2, 64, 128, 128, 128, 64, 64, 1, 0, 1);
    // conv3: 128->128, k3 s1 p1, no act
    conv2d_kernel<3, 1, 16, 8><<<dim3(4, 4, N * (128 / 16)), blk>>>(
        b2, enc_w3, enc_b3, nullptr, b3, 128, 64, 64, 128, 64, 64, 1, 0, 0);
    // residual stack x2 (3x3 at OCB=8 -> grid 2048, grid-starvation fix)
    for (int i = 0; i < 2; i++) {
        const float* w1p = enc_rw1 + (size_t)i * 32 * 128 * 9;
        const float* b1p = enc_rb1 + i * 32;
        const float* w2p = enc_rw2 + (size_t)i * 128 * 32;
        const float* b2p = enc_rb2 + i * 128;
        conv2d_kernel<3, 1, 8, 8><<<dim3(4, 4, N * (32 / 8)), blk>>>(
            b3, w1p, b1p, nullptr, b4, 128, 64, 64, 32, 64, 64, 1, 1, 0);
        conv2d_kernel<1, 1, 16, 16><<<dim3(4, 4, N * (128 / 16)), blk>>>(
            b4, w2p, b2p, b3, b3, 32, 64, 64, 128, 64, 64, 0, 1, (i == 1) ? 1 : 0);
    }
    // pre-VQ 1x1: 128->64
    conv2d_kernel<1, 1, 16, 16><<<dim3(4, 4, N * (64 / 16)), blk>>>(
        b3, pvq_w, pvq_b, nullptr, bz, 128, 64, 64, 64, 64, 64, 0, 0, 0);

    // ---- VQ ----
    vq_prep_kernel<<<2, 256>>>(codebook, pe);
    vq_kernel<<<1024, 128>>>(bz, codebook, pe, bq, pbs);

    // ---- Decoder ----
    // dec conv1: 64->128, k3 s1 p1, no act
    conv2d_kernel<3, 1, 16, 8><<<dim3(4, 4, N * (128 / 16)), blk>>>(
        bq, dec_w1, dec_b1, nullptr, bd, 64, 64, 64, 128, 64, 64, 1, 0, 0);
    // residual stack x2
    for (int i = 0; i < 2; i++) {
        const float* w1p = dec_rw1 + (size_t)i * 32 * 128 * 9;
        const float* b1p = dec_rb1 + i * 32;
        const float* w2p = dec_rw2 + (size_t)i * 128 * 32;
        const float* b2p = dec_rb2 + i * 128;
        conv2d_kernel<3, 1, 8, 8><<<dim3(4, 4, N * (32 / 8)), blk>>>(
            bd, w1p, b1p, nullptr, b4, 128, 64, 64, 32, 64, 64, 1, 1, 0);
        conv2d_kernel<1, 1, 16, 16><<<dim3(4, 4, N * (128 / 16)), blk>>>(
            b4, w2p, b2p, bd, bd, 32, 64, 64, 128, 64, 64, 0, 1, (i == 1) ? 1 : 0);
    }
    // deconv1: 128->64, relu  (64 -> 128)
    deconv_k4s2_kernel<8, 8><<<dim3(4, 4, N * (64 / 8)), dblk>>>(
        bd, dt1_w, dt1_b, b1, 128, 64, 64, 64, 1);
    // deconv2: 64->3, tanh  (128 -> 256), COB=4
    deconv_k4s2_kernel<4, 8><<<dim3(8, 8, N * 1), dblk>>>(
        b1, dt2_w, dt2_b, outp, 64, 128, 128, 3, 2);

    // vq_loss -> last output element (deterministic fixed-order reduction)
    finalize_kernel<<<1, 256>>>(pbs, outp + (out_size - 1));
}